// round 14
// baseline (speedup 1.0000x reference)
#include <cuda_runtime.h>

// ---------------------------------------------------------------------------
// InformedSender: image path (2 tiny GEMMs) + 2-game, 2-layer GAT graph path.
// Key simplification: output depends only on layer-1 head 0 and layer-2 head 0,
// so each GAT layer is a single-head 64-dim GAT.
//
// Graph path per game:
//   h1 = node_feat @ W1[:, :64]           -> el1 = h1.al1[0], er1 = h1.ar1[0]
//   CSR by dst (built once, reused by both layers)
//   r1 = relu(softmax-aggregate(h1) + b1[0])
//   h2 = r1 @ W2[:, :64]                  -> el2, er2
//   gr_sum += softmax-aggregate(h2)   (mean + b2[0] applied at the end)
// ---------------------------------------------------------------------------

#define NGAMES 2
#define HID 64
#define MAXN 20000
#define MAXE 320000

__device__ float g_h   [NGAMES * MAXN * HID];
__device__ float g_r1  [NGAMES * MAXN * HID];
__device__ float g_el  [NGAMES * MAXN];
__device__ float g_er  [NGAMES * MAXN];
__device__ int   g_deg [NGAMES * MAXN];
__device__ int   g_offs[NGAMES * (MAXN + 1)];
__device__ int   g_cur [NGAMES * MAXN];
__device__ int   g_csrc[NGAMES * MAXE];
__device__ float g_E    [128];   // image embed E: [2][64]
__device__ float g_grsum[128];   // per-game node-sum of layer-2 output

// ---------------------------------------------------------------------------
__global__ void init_kernel(int N) {
    int i = blockIdx.x * blockDim.x + threadIdx.x;
    if (i < NGAMES * N) g_deg[i] = 0;
    if (i < 128) { g_E[i] = 0.f; g_grsum[i] = 0.f; }
}

// E[g][c] = sum_k x[g][k] * W[k][c]   (W: [F,64] row-major), partials by k-chunk
__global__ void imgE_kernel(const float* __restrict__ x,
                            const float* __restrict__ W, int F) {
    int g = blockIdx.y;
    int c = threadIdx.x;              // 0..63
    int k0 = blockIdx.x * 64;
    int kmax = F - k0; if (kmax > 64) kmax = 64;
    const float* xg = x + (size_t)g * F;
    float acc = 0.f;
    for (int kk = 0; kk < kmax; ++kk) {
        int k = k0 + kk;
        acc += xg[k] * W[(size_t)k * 64 + c];
    }
    atomicAdd(&g_E[g * 64 + c], acc);
}

// histogram of dst
__global__ void hist_kernel(const int* __restrict__ dst, int N, int E) {
    int g = blockIdx.y;
    int e = blockIdx.x * blockDim.x + threadIdx.x;
    if (e < E) atomicAdd(&g_deg[g * N + dst[(size_t)g * E + e]], 1);
}

// exclusive scan of deg -> offs (and cursor copy). One block (1024 thr) per game.
__global__ void scan_kernel(int N) {
    int g = blockIdx.x;
    const int* dg = g_deg + g * N;
    int* of = g_offs + g * (N + 1);
    int* cu = g_cur  + g * N;
    __shared__ int wsum[32];
    __shared__ int s_carry;
    int tid = threadIdx.x, lane = tid & 31, wid = tid >> 5;
    int nwarp = blockDim.x >> 5;
    if (tid == 0) s_carry = 0;
    __syncthreads();
    for (int base = 0; base < N; base += blockDim.x) {
        int i = base + tid;
        int d = (i < N) ? dg[i] : 0;
        int x = d;
        #pragma unroll
        for (int o = 1; o < 32; o <<= 1) {
            int y = __shfl_up_sync(0xffffffffu, x, o);
            if (lane >= o) x += y;
        }
        if (lane == 31) wsum[wid] = x;
        __syncthreads();
        if (wid == 0) {
            int wv = (lane < nwarp) ? wsum[lane] : 0;
            #pragma unroll
            for (int o = 1; o < 32; o <<= 1) {
                int y = __shfl_up_sync(0xffffffffu, wv, o);
                if (lane >= o) wv += y;
            }
            wsum[lane] = wv;
        }
        __syncthreads();
        int woff = wid ? wsum[wid - 1] : 0;
        int excl = x - d + woff;
        int carry = s_carry;
        if (i < N) { of[i] = carry + excl; cu[i] = carry + excl; }
        __syncthreads();
        if (tid == 0) s_carry = carry + wsum[nwarp - 1];
        __syncthreads();
    }
    if (threadIdx.x == 0) of[N] = s_carry;
}

// scatter src indices into dst-sorted CSR
__global__ void scatter_kernel(const int* __restrict__ src,
                               const int* __restrict__ dst, int N, int E) {
    int g = blockIdx.y;
    int e = blockIdx.x * blockDim.x + threadIdx.x;
    if (e < E) {
        int d = dst[(size_t)g * E + e];
        int pos = atomicAdd(&g_cur[g * N + d], 1);
        g_csrc[(size_t)g * E + pos] = src[(size_t)g * E + e];
    }
}

// layer-1 projection: h = feat[N,3] @ W1[:, :64]; el/er dot-products. Warp/node.
__global__ void gat1_h_kernel(const float* __restrict__ nf,
                              const float* __restrict__ W,   // [3,128]
                              const float* __restrict__ al,  // head0: first 64
                              const float* __restrict__ ar,
                              int N) {
    int lane = threadIdx.x & 31;
    int n = blockIdx.x * (blockDim.x >> 5) + (threadIdx.x >> 5);
    int g = blockIdx.y;
    if (n >= N) return;
    const float* f = nf + ((size_t)g * N + n) * 3;
    float f0 = f[0], f1 = f[1], f2 = f[2];
    int c0 = lane, c1 = lane + 32;
    float h0 = f0 * W[c0] + f1 * W[128 + c0] + f2 * W[256 + c0];
    float h1 = f0 * W[c1] + f1 * W[128 + c1] + f2 * W[256 + c1];
    float* hp = g_h + ((size_t)g * N + n) * HID;
    hp[c0] = h0; hp[c1] = h1;
    float pel = h0 * al[c0] + h1 * al[c1];
    float per = h0 * ar[c0] + h1 * ar[c1];
    #pragma unroll
    for (int o = 16; o; o >>= 1) {
        pel += __shfl_down_sync(0xffffffffu, pel, o);
        per += __shfl_down_sync(0xffffffffu, per, o);
    }
    if (lane == 0) { g_el[g * N + n] = pel; g_er[g * N + n] = per; }
}

// layer-2 projection: h2 = r1[N,64] @ W2[:, :64]; el/er. Warp/node, W in smem.
__global__ void gat2_h_kernel(const float* __restrict__ W,   // [64,128]
                              const float* __restrict__ al,
                              const float* __restrict__ ar,
                              int N) {
    __shared__ float Ws[64 * 64];
    int tid = threadIdx.x;
    for (int i = tid; i < 64 * 64; i += blockDim.x) {
        int k = i >> 6, c = i & 63;
        Ws[i] = W[(size_t)k * 128 + c];
    }
    __syncthreads();
    int lane = tid & 31;
    int n = blockIdx.x * (blockDim.x >> 5) + (tid >> 5);
    int g = blockIdx.y;
    if (n < N) {
        const float* rp = g_r1 + ((size_t)g * N + n) * HID;
        float v0 = rp[lane], v1 = rp[lane + 32];
        float acc0 = 0.f, acc1 = 0.f;
        #pragma unroll
        for (int k = 0; k < 32; ++k) {
            float rk = __shfl_sync(0xffffffffu, v0, k);
            acc0 += rk * Ws[k * 64 + lane];
            acc1 += rk * Ws[k * 64 + lane + 32];
        }
        #pragma unroll
        for (int k = 0; k < 32; ++k) {
            float rk = __shfl_sync(0xffffffffu, v1, k);
            acc0 += rk * Ws[(k + 32) * 64 + lane];
            acc1 += rk * Ws[(k + 32) * 64 + lane + 32];
        }
        float* hp = g_h + ((size_t)g * N + n) * HID;
        hp[lane] = acc0; hp[lane + 32] = acc1;
        float pel = acc0 * al[lane] + acc1 * al[lane + 32];
        float per = acc0 * ar[lane] + acc1 * ar[lane + 32];
        #pragma unroll
        for (int o = 16; o; o >>= 1) {
            pel += __shfl_down_sync(0xffffffffu, pel, o);
            per += __shfl_down_sync(0xffffffffu, per, o);
        }
        if (lane == 0) { g_el[g * N + n] = pel; g_er[g * N + n] = per; }
    }
}

// Hot kernel: warp-per-dst-node online-softmax aggregation over in-edges.
// LAYER==1: write r1 = relu(out + b). LAYER==2: accumulate node-sum into grsum.
template <int LAYER>
__global__ void agg_kernel(const float* __restrict__ bias, int N, int E) {
    int lane = threadIdx.x & 31;
    int n = blockIdx.x * (blockDim.x >> 5) + (threadIdx.x >> 5);
    int g = blockIdx.y;
    __shared__ float sacc[64];
    if (LAYER == 2) {
        if (threadIdx.x < 64) sacc[threadIdx.x] = 0.f;
        __syncthreads();
    }
    float o0 = 0.f, o1 = 0.f;
    bool valid = (n < N);
    if (valid) {
        const float2* h2 = (const float2*)(g_h + (size_t)g * N * HID);
        const float*  elg = g_el + (size_t)g * N;
        const int*    off = g_offs + (size_t)g * (N + 1);
        const int*    cs  = g_csrc + (size_t)g * E;
        float ern = g_er[(size_t)g * N + n];
        int j = off[n], jend = off[n + 1];
        float m = -1e30f, den = 0.f, a0 = 0.f, a1 = 0.f;
        #pragma unroll 2
        for (; j < jend; ++j) {
            int s = cs[j];
            float e = elg[s] + ern;
            e = (e >= 0.f) ? e : 0.2f * e;           // leaky_relu slope 0.2
            float w;
            if (e > m) {
                float sc = __expf(m - e);
                den *= sc; a0 *= sc; a1 *= sc;
                m = e; w = 1.f;
            } else {
                w = __expf(e - m);
            }
            float2 hv = h2[(size_t)s * 32 + lane];
            den += w;
            a0 += w * hv.x;
            a1 += w * hv.y;
        }
        float inv = (den > 0.f) ? 1.f / den : 0.f;
        o0 = a0 * inv; o1 = a1 * inv;
    }
    if (LAYER == 1) {
        if (valid) {
            float b0 = bias[2 * lane], b1 = bias[2 * lane + 1];
            float r0 = fmaxf(o0 + b0, 0.f);
            float r1v = fmaxf(o1 + b1, 0.f);
            float2* op = (float2*)(g_r1 + ((size_t)g * N + n) * HID);
            op[lane] = make_float2(r0, r1v);
        }
    } else {
        if (valid) {
            atomicAdd(&sacc[2 * lane], o0);
            atomicAdd(&sacc[2 * lane + 1], o1);
        }
        __syncthreads();
        if (threadIdx.x < 64) atomicAdd(&g_grsum[g * 64 + threadIdx.x], sacc[threadIdx.x]);
    }
}

// Final fusion: gr linear + image convs + output linear + log_softmax. 1 block.
__global__ void final_kernel(const float* __restrict__ b2,     // gat2_b (head0 = first 64)
                             const float* __restrict__ gr_w,   // [128,64]
                             const float* __restrict__ gr_b,   // [64]
                             const float* __restrict__ cw1,    // [64,2]
                             const float* __restrict__ cw2,    // [64]
                             const float* __restrict__ Wout,   // [128,V]
                             float* __restrict__ out, int N, int V) {
    __shared__ float grv[128];
    __shared__ float hvec[128];
    __shared__ float logits[16];
    __shared__ float sm[2];
    int t = threadIdx.x;
    float invN = 1.f / (float)N;
    grv[t] = g_grsum[t] * invN + b2[t & 63];
    __syncthreads();
    if (t < 64) {
        // gr2 = grv @ gr_lin1_w + gr_lin1_b
        float acc = gr_b[t];
        #pragma unroll 4
        for (int k = 0; k < 128; ++k) acc += grv[k] * gr_w[k * 64 + t];
        hvec[t] = acc;
    } else {
        // image path: h1 = leaky(conv1_w @ E), h2 = leaky(conv2_w @ h1)
        int j = t - 64;
        float E0 = g_E[j], E1 = g_E[64 + j];
        float acc = 0.f;
        #pragma unroll 4
        for (int i = 0; i < 64; ++i) {
            float v = cw1[2 * i] * E0 + cw1[2 * i + 1] * E1;
            v = (v >= 0.f) ? v : 0.01f * v;
            acc += cw2[i] * v;
        }
        hvec[t] = (acc >= 0.f) ? acc : 0.01f * acc;
    }
    __syncthreads();
    if (t < V) {
        float acc = 0.f;
        #pragma unroll 4
        for (int k = 0; k < 128; ++k) acc += hvec[k] * Wout[k * V + t];
        logits[t] = acc;
    }
    __syncthreads();
    if (t == 0) {
        float mx = -1e30f;
        for (int v = 0; v < V; ++v) mx = fmaxf(mx, logits[v]);
        float s = 0.f;
        for (int v = 0; v < V; ++v) s += expf(logits[v] - mx);
        sm[0] = mx; sm[1] = logf(s);
    }
    __syncthreads();
    if (t < V) out[t] = logits[t] - sm[0] - sm[1];
}

// ---------------------------------------------------------------------------
extern "C" void kernel_launch(void* const* d_in, const int* in_sizes, int n_in,
                              void* d_out, int out_size) {
    const float* x        = (const float*)d_in[0];
    const float* node_feat= (const float*)d_in[1];
    const int*   src      = (const int*)  d_in[2];
    const int*   dst      = (const int*)  d_in[3];
    const float* im_lin1_w= (const float*)d_in[4];
    const float* conv1_w  = (const float*)d_in[5];
    const float* conv2_w  = (const float*)d_in[6];
    const float* gat1_w   = (const float*)d_in[7];
    const float* gat1_al  = (const float*)d_in[8];
    const float* gat1_ar  = (const float*)d_in[9];
    const float* gat1_b   = (const float*)d_in[10];
    const float* gat2_w   = (const float*)d_in[11];
    const float* gat2_al  = (const float*)d_in[12];
    const float* gat2_ar  = (const float*)d_in[13];
    const float* gat2_b   = (const float*)d_in[14];
    const float* gr_lin1_w= (const float*)d_in[15];
    const float* gr_lin1_b= (const float*)d_in[16];
    const float* im_lin2_w= (const float*)d_in[17];
    float* out = (float*)d_out;

    const int F = in_sizes[0] / NGAMES;        // 4096
    const int N = in_sizes[1] / (NGAMES * 3);  // 20000
    const int E = in_sizes[2] / NGAMES;        // 320000
    const int V = in_sizes[17] / 128;          // 10

    // 0) init scratch
    {
        int tot = NGAMES * N; if (tot < 128) tot = 128;
        init_kernel<<<(tot + 255) / 256, 256>>>(N);
    }
    // 1) image embed partials (independent of graph path)
    {
        dim3 grid((F + 63) / 64, NGAMES);
        imgE_kernel<<<grid, 64>>>(x, im_lin1_w, F);
    }
    // 2) CSR build
    {
        dim3 grid((E + 255) / 256, NGAMES);
        hist_kernel<<<grid, 256>>>(dst, N, E);
        scan_kernel<<<NGAMES, 1024>>>(N);
        scatter_kernel<<<grid, 256>>>(src, dst, N, E);
    }
    // 3) layer-1 projection
    {
        dim3 grid((N + 7) / 8, NGAMES);
        gat1_h_kernel<<<grid, 256>>>(node_feat, gat1_w, gat1_al, gat1_ar, N);
    }
    // 4) layer-1 aggregation -> r1
    {
        dim3 grid((N + 7) / 8, NGAMES);
        agg_kernel<1><<<grid, 256>>>(gat1_b, N, E);
    }
    // 5) layer-2 projection
    {
        dim3 grid((N + 7) / 8, NGAMES);
        gat2_h_kernel<<<grid, 256>>>(gat2_w, gat2_al, gat2_ar, N);
    }
    // 6) layer-2 aggregation -> grsum
    {
        dim3 grid((N + 7) / 8, NGAMES);
        agg_kernel<2><<<grid, 256>>>(nullptr, N, E);
    }
    // 7) final fusion
    final_kernel<<<1, 128>>>(gat2_b, gr_lin1_w, gr_lin1_b,
                             conv1_w, conv2_w, im_lin2_w, out, N, V);
}